// round 12
// baseline (speedup 1.0000x reference)
#include <cuda_runtime.h>
#include <cuda_fp16.h>
#include <cstdint>

#define CDIM 256
#define MAX_ROWS 32768
#define MAX_KCB  4096

#define M_TILE 128
#define N_CHUNK 256
#define KT 64                 // halfs per k-window (= 128 B per row)
#define ROWB 128
#define THREADS 256
#define MARGIN 0.3f

// smem layout (occ 1): A-resident 4 subtiles (h0, kc 0..3), 4 B stages, red
#define SM_A    0
#define ASUB    16384                       // 128 rows * 128 B
#define SM_B    (4 * ASUB)                  // 65536
#define BSTG    (N_CHUNK * ROWB)            // 32768
#define NBUF    4
#define SM_RED  (SM_B + NBUF * BSTG)        // 196608
#define SMEM_TOTAL (SM_RED + 128 * 8 + 128 * 4)   // 198144

// ---------------- device globals ----------------
__device__ int    g_idx[MAX_ROWS];
__device__ int    g_flag[MAX_ROWS];
__device__ float  g_e2[MAX_KCB];
__device__ float  g_partial[MAX_ROWS];
__device__ float  g_x2s[MAX_ROWS];
__device__ __half g_c0[MAX_KCB * CDIM];

// ---------------- PTX helpers ----------------
__device__ __forceinline__ uint32_t smem_u32(const void* p) {
    uint32_t a;
    asm("{ .reg .u64 t; cvta.to.shared.u64 t, %1; cvt.u32.u64 %0, t; }"
        : "=r"(a) : "l"(p));
    return a;
}

#define CP_ASYNC16(dst, src) \
    asm volatile("cp.async.cg.shared.global [%0], [%1], 16;" :: "r"(dst), "l"(src))
#define CP_COMMIT()  asm volatile("cp.async.commit_group;")
#define CP_WAIT2()   asm volatile("cp.async.wait_group 2;")
#define CP_WAIT1()   asm volatile("cp.async.wait_group 1;")
#define CP_WAIT0()   asm volatile("cp.async.wait_group 0;")

#define LDSM_X4(r0, r1, r2, r3, addr)                                          \
    asm volatile("ldmatrix.sync.aligned.m8n8.x4.shared.b16 {%0,%1,%2,%3}, [%4];" \
        : "=r"(r0), "=r"(r1), "=r"(r2), "=r"(r3) : "r"(addr))

#define MMA16816(d, a0, a1, a2, a3, b0, b1)                                    \
    asm volatile("mma.sync.aligned.m16n8k16.row.col.f32.f16.f16.f32 "          \
        "{%0,%1,%2,%3},{%4,%5,%6,%7},{%8,%9},{%0,%1,%2,%3};"                   \
        : "+f"((d)[0]), "+f"((d)[1]), "+f"((d)[2]), "+f"((d)[3])               \
        : "r"(a0), "r"(a1), "r"(a2), "r"(a3), "r"(b0), "r"(b1))

__device__ __forceinline__ uint32_t fkey(float f) {
    uint32_t u = __float_as_uint(f);
    return u ^ ((u & 0x80000000u) ? 0xFFFFFFFFu : 0x80000000u);
}
__device__ __forceinline__ float unfkey(uint32_t k) {
    uint32_t u = (k & 0x80000000u) ? (k ^ 0x80000000u) : ~k;
    return __uint_as_float(u);
}

// ---------------------------------------------------------------------------
__global__ void convert_kernel(const float* __restrict__ src,
                               __half* __restrict__ d0, int n) {
    int i = blockIdx.x * blockDim.x + threadIdx.x;
    if (i < n) d0[i] = __float2half_rn(src[i]);
}

__global__ void rownorm_kernel(const float* __restrict__ src,
                               float* __restrict__ dst, int rows) {
    int w = (blockIdx.x * blockDim.x + threadIdx.x) >> 5;
    int lane = threadIdx.x & 31;
    if (w >= rows) return;
    const float4* p = (const float4*)(src + (size_t)w * CDIM);
    float s = 0.f;
    #pragma unroll
    for (int i = lane; i < CDIM / 4; i += 32) {
        float4 v = p[i];
        s += v.x * v.x + v.y * v.y + v.z * v.z + v.w * v.w;
    }
    #pragma unroll
    for (int o = 16; o; o >>= 1) s += __shfl_xor_sync(0xffffffffu, s, o);
    if (lane == 0) dst[w] = s;
}

// ---------------------------------------------------------------------------
// Phase 1: approx GEMM (h0*c0 only, fp32 acc) + top-2 argmin + margin flag.
// 256 threads = 8 warps as 2(m) x 4(n), warp tile 64x64.
// ---------------------------------------------------------------------------
__global__ void __launch_bounds__(THREADS, 1)
mma_argmin_kernel(const float* __restrict__ x, int kcb) {
    extern __shared__ char smem[];
    const uint32_t sb = smem_u32(smem);
    const int tid = threadIdx.x;
    const int wid = tid >> 5, lane = tid & 31;
    const int warp_m = wid & 1, warp_n = wid >> 1;     // 2 x 4
    const int rowBase = blockIdx.x * M_TILE;
    const int nChunks = kcb / N_CHUNK;            // 4
    const int S = nChunks * 4;                    // 16 B-stages

    // ---- B stage loader (c0 only) ----
    auto load_B = [&](int s) {
        const int c = s >> 2, kc = s & 3;
        const char* bsrc = (const char*)(g_c0 + (size_t)(c * N_CHUNK) * CDIM + kc * KT);
        const uint32_t bb = sb + SM_B + (s % NBUF) * BSTG;
        #pragma unroll
        for (int i = 0; i < 8; i++) {
            int u = tid + THREADS * i;
            int r = u >> 3, q = u & 7;
            CP_ASYNC16(bb + r * ROWB + ((q ^ (r & 7)) * 16),
                       bsrc + (size_t)r * (CDIM * 2) + q * 16);
        }
        CP_COMMIT();
    };

    load_B(0);
    load_B(1);
    load_B(2);

    // ---- on-the-fly A convert: fp32 -> h0 subtiles (kc 0..3) ----
    {
        const float* xsrc = x + (size_t)rowBase * CDIM;
        #pragma unroll 4
        for (int i = 0; i < 32; i++) {
            int u = tid + THREADS * i;          // float4 index
            int row = u >> 6;
            int coloff = (u & 63) * 4;
            float4 v = *(const float4*)(xsrc + (size_t)row * CDIM + coloff);
            __half2 lo = __halves2half2(__float2half_rn(v.x), __float2half_rn(v.y));
            __half2 hi = __halves2half2(__float2half_rn(v.z), __float2half_rn(v.w));
            int kc = coloff >> 6;
            int c  = coloff & 63;
            uint32_t off = (uint32_t)row * ROWB +
                           ((uint32_t)(((c >> 3) ^ (row & 7))) * 16) + ((c & 7) * 2);
            uint32_t d0 = sb + SM_A + kc * ASUB + off;
            asm volatile("st.shared.v2.b32 [%0], {%1,%2};" ::
                "r"(d0), "r"(*(uint32_t*)&lo), "r"(*(uint32_t*)&hi));
        }
    }

    // red arrays
    unsigned long long* red1 = (unsigned long long*)(smem + SM_RED);
    unsigned int* red2 = (unsigned int*)(smem + SM_RED + 128 * 8);
    for (int i = tid; i < M_TILE; i += THREADS) {
        red1[i] = 0xFFFFFFFFFFFFFFFFull;
        red2[i] = 0xFFFFFFFFu;
    }

    // ldmatrix address components
    const int lrow = lane & 15;
    const int hi   = lane >> 4;
    const int xorl = lrow & 7;
    uint32_t arow[4], brow[4];
    #pragma unroll
    for (int mt = 0; mt < 4; mt++)
        arow[mt] = (warp_m * 64 + mt * 16 + lrow) * ROWB;
    #pragma unroll
    for (int p = 0; p < 4; p++)
        brow[p] = (warp_n * 64 + p * 16 + lrow) * ROWB;

    float acc[4][8][4];
    #pragma unroll
    for (int mt = 0; mt < 4; mt++)
        #pragma unroll
        for (int nt = 0; nt < 8; nt++)
            #pragma unroll
            for (int e = 0; e < 4; e++) acc[mt][nt][e] = 0.f;

    float best[8], best2[8];
    int   bidx[8];
    #pragma unroll
    for (int i = 0; i < 8; i++) { best[i] = 3.4e38f; best2[i] = 3.4e38f; bidx[i] = 0; }

    for (int s = 0; s < S; s++) {
        if (s <= S - 3) CP_WAIT2();
        else if (s == S - 2) CP_WAIT1();
        else CP_WAIT0();
        __syncthreads();
        if (s + 3 < S) load_B(s + 3);

        const int kc = s & 3;
        const uint32_t ab = sb + SM_A + kc * ASUB;
        const uint32_t bb = sb + SM_B + (s % NBUF) * BSTG;

        #pragma unroll
        for (int ks = 0; ks < 4; ks++) {
            const uint32_t koff = ((uint32_t)((ks * 2 + hi) ^ xorl)) * 16;
            uint32_t ar[4][4];
            uint32_t br[8][2];
            #pragma unroll
            for (int p = 0; p < 4; p++) {
                uint32_t r0, r1, r2, r3;
                LDSM_X4(r0, r1, r2, r3, bb + brow[p] + koff);
                br[2 * p][0] = r0; br[2 * p][1] = r2;
                br[2 * p + 1][0] = r1; br[2 * p + 1][1] = r3;
            }
            #pragma unroll
            for (int mt = 0; mt < 4; mt++)
                LDSM_X4(ar[mt][0], ar[mt][1], ar[mt][2], ar[mt][3],
                        ab + arow[mt] + koff);
            #pragma unroll
            for (int mt = 0; mt < 4; mt++)
                #pragma unroll
                for (int nt = 0; nt < 8; nt++)
                    MMA16816(acc[mt][nt],
                             ar[mt][0], ar[mt][1], ar[mt][2], ar[mt][3],
                             br[nt][0], br[nt][1]);
        }

        // ---- chunk epilogue: score + top-2 update ----
        if (kc == 3) {
            const int c = s >> 2;
            const int colBase = c * N_CHUNK + warp_n * 64 + (lane & 3) * 2;
            #pragma unroll
            for (int nt = 0; nt < 8; nt++) {
                const int n0 = colBase + nt * 8;
                float2 e2v = *(const float2*)&g_e2[n0];
                #pragma unroll
                for (int mt = 0; mt < 4; mt++) {
                    float sc[4];
                    sc[0] = e2v.x - 2.f * acc[mt][nt][0];
                    sc[1] = e2v.y - 2.f * acc[mt][nt][1];
                    sc[2] = e2v.x - 2.f * acc[mt][nt][2];
                    sc[3] = e2v.y - 2.f * acc[mt][nt][3];
                    #pragma unroll
                    for (int e = 0; e < 4; e++) {
                        int slot = mt * 2 + (e >> 1);
                        int col  = n0 + (e & 1);
                        if (sc[e] < best[slot]) {
                            best2[slot] = best[slot];
                            best[slot] = sc[e];
                            bidx[slot] = col;
                        } else if (sc[e] < best2[slot]) {
                            best2[slot] = sc[e];
                        }
                        acc[mt][nt][e] = 0.f;
                    }
                }
            }
        }
    }

    // ---- cross-thread top-2 merge ----
    __syncthreads();
    #pragma unroll
    for (int slot = 0; slot < 8; slot++) {
        int mt = slot >> 1, h = slot & 1;
        int rl = warp_m * 64 + mt * 16 + (lane >> 2) + h * 8;
        unsigned long long pk =
            ((unsigned long long)fkey(best[slot]) << 32) |
            (unsigned long long)(uint32_t)bidx[slot];
        atomicMin(&red1[rl], pk);
    }
    __syncthreads();
    #pragma unroll
    for (int slot = 0; slot < 8; slot++) {
        int mt = slot >> 1, h = slot & 1;
        int rl = warp_m * 64 + mt * 16 + (lane >> 2) + h * 8;
        int widx = (int)(red1[rl] & 0xFFFFFFFFu);
        float cand = (bidx[slot] == widx) ? best2[slot] : best[slot];
        atomicMin(&red2[rl], fkey(cand));
    }
    __syncthreads();
    if (tid < M_TILE) {
        unsigned long long pk = red1[tid];
        float b1 = unfkey((uint32_t)(pk >> 32));
        float b2 = unfkey(red2[tid]);
        int row = rowBase + tid;
        g_idx[row] = (int)(pk & 0xFFFFFFFFu);
        g_partial[row] = g_x2s[row] + b1;
        g_flag[row] = (b2 - b1 < MARGIN) ? 1 : 0;
    }
}

// ---------------------------------------------------------------------------
// Phase 2: exact fp32 re-scoring of flagged rows only.
// ---------------------------------------------------------------------------
__global__ void exact_fallback_kernel(const float* __restrict__ x,
                                      const float* __restrict__ cb, int kcb) {
    int row = blockIdx.x;
    if (!g_flag[row]) return;
    __shared__ float4 xs[CDIM / 4];
    __shared__ unsigned long long red;
    int t = threadIdx.x;   // 256
    if (t == 0) red = 0xFFFFFFFFFFFFFFFFull;
    if (t < CDIM / 4) xs[t] = ((const float4*)(x + (size_t)row * CDIM))[t];
    __syncthreads();
    for (int k = t; k < kcb; k += 256) {
        const float4* c4 = (const float4*)(cb + (size_t)k * CDIM);
        float s = 0.f;
        #pragma unroll 8
        for (int i = 0; i < CDIM / 4; i++) {
            float4 c = c4[i], xv = xs[i];
            s += c.x * xv.x + c.y * xv.y + c.z * xv.z + c.w * xv.w;
        }
        float sc = g_e2[k] - 2.f * s;
        unsigned long long pk =
            ((unsigned long long)fkey(sc) << 32) | (unsigned long long)(uint32_t)k;
        atomicMin(&red, pk);
    }
    __syncthreads();
    if (t == 0) {
        unsigned long long pk = red;
        g_idx[row] = (int)(pk & 0xFFFFFFFFu);
        g_partial[row] = g_x2s[row] + unfkey((uint32_t)(pk >> 32));
    }
}

// ---------------------------------------------------------------------------
__global__ void gather_kernel(const float* __restrict__ cbk,
                              float* __restrict__ outq,
                              float* __restrict__ outidx) {
    int row = blockIdx.x;
    int t = threadIdx.x;   // 64
    int idx = g_idx[row];
    float4 q = *(const float4*)(cbk + (size_t)idx * CDIM + t * 4);
    *(float4*)(outq + (size_t)row * CDIM + t * 4) = q;
    if (t == 0 && outidx) outidx[row] = (float)idx;
}

__global__ void finalize_kernel(float* __restrict__ outloss, int rows, int qn) {
    __shared__ double sh[1024];
    const float4* p4 = (const float4*)g_partial;
    double s = 0.0;
    for (int i = threadIdx.x; i < rows / 4; i += 1024) {
        float4 v = p4[i];
        s += (double)v.x + (double)v.y + (double)v.z + (double)v.w;
    }
    sh[threadIdx.x] = s;
    __syncthreads();
    for (int st = 512; st; st >>= 1) {
        if (threadIdx.x < st) sh[threadIdx.x] += sh[threadIdx.x + st];
        __syncthreads();
    }
    if (threadIdx.x == 0)
        *outloss = (float)(1.25 * sh[0] / (double)qn);
}

// ---------------------------------------------------------------------------
extern "C" void kernel_launch(void* const* d_in, const int* in_sizes, int n_in,
                              void* d_out, int out_size) {
    const float* x  = (const float*)d_in[0];
    const float* cb = (const float*)d_in[1];
    float* out = (float*)d_out;

    const int qn   = in_sizes[0];          // 8*4096*256
    const int kcb  = in_sizes[1] / CDIM;   // 1024
    const int rows = qn / CDIM;            // 32768

    __half *pc0;
    float *pe2, *px2;
    cudaGetSymbolAddress((void**)&pc0, g_c0);
    cudaGetSymbolAddress((void**)&pe2, g_e2);
    cudaGetSymbolAddress((void**)&px2, g_x2s);

    convert_kernel<<<(kcb * CDIM + 255) / 256, 256>>>(cb, pc0, kcb * CDIM);
    rownorm_kernel<<<(kcb * 32 + 255) / 256, 256>>>(cb, pe2, kcb);
    rownorm_kernel<<<(rows * 32 + 255) / 256, 256>>>(x, px2, rows);

    cudaFuncSetAttribute(mma_argmin_kernel,
                         cudaFuncAttributeMaxDynamicSharedMemorySize, SMEM_TOTAL);
    mma_argmin_kernel<<<rows / M_TILE, THREADS, SMEM_TOTAL>>>(x, kcb);

    exact_fallback_kernel<<<rows, 256>>>(x, cb, kcb);

    bool has_loss = out_size >= qn + 1;
    bool has_idx  = out_size >= qn + 1 + rows;
    float* outidx = has_idx ? (out + qn + 1) : nullptr;

    gather_kernel<<<rows, 64>>>(cb, out, outidx);
    if (has_loss)
        finalize_kernel<<<1, 1024>>>(out + qn, rows, qn);
}

// round 13
// speedup vs baseline: 1.8357x; 1.8357x over previous
#include <cuda_runtime.h>
#include <cuda_fp16.h>
#include <cstdint>

#define CDIM 256
#define MAX_ROWS 32768
#define MAX_KCB  4096

#define M_TILE 128
#define N_CHUNK 256
#define KT 64                 // halfs per k-window (= 128 B per row)
#define ROWB 128
#define THREADS 256
#define MARGIN 0.1f
#define FB_R 8

// smem: A-resident 8 subtiles (h0 kc0..3, h1 kc0..3), 3 B stages, red
#define SM_A    0
#define ASUB    16384                       // 128 rows * 128 B
#define SM_B    (8 * ASUB)                  // 131072
#define BSTG    (N_CHUNK * ROWB)            // 32768
#define NBUF    3
#define SM_RED  (SM_B + NBUF * BSTG)        // 229376
#define SMEM_TOTAL (SM_RED + 128 * 8 + 128 * 4)   // 230912 <= 232448

// ---------------- device globals ----------------
__device__ int    g_idx[MAX_ROWS];
__device__ int    g_list[MAX_ROWS];
__device__ int    g_cnt;
__device__ float  g_e2[MAX_KCB];
__device__ float  g_partial[MAX_ROWS];
__device__ float  g_x2s[MAX_ROWS];
__device__ __half g_c0[MAX_KCB * CDIM];

// ---------------- PTX helpers ----------------
__device__ __forceinline__ uint32_t smem_u32(const void* p) {
    uint32_t a;
    asm("{ .reg .u64 t; cvta.to.shared.u64 t, %1; cvt.u32.u64 %0, t; }"
        : "=r"(a) : "l"(p));
    return a;
}

#define CP_ASYNC16(dst, src) \
    asm volatile("cp.async.cg.shared.global [%0], [%1], 16;" :: "r"(dst), "l"(src))
#define CP_COMMIT()  asm volatile("cp.async.commit_group;")
#define CP_WAIT1()   asm volatile("cp.async.wait_group 1;")
#define CP_WAIT0()   asm volatile("cp.async.wait_group 0;")

#define LDSM_X4(r0, r1, r2, r3, addr)                                          \
    asm volatile("ldmatrix.sync.aligned.m8n8.x4.shared.b16 {%0,%1,%2,%3}, [%4];" \
        : "=r"(r0), "=r"(r1), "=r"(r2), "=r"(r3) : "r"(addr))

#define MMA16816(d, a0, a1, a2, a3, b0, b1)                                    \
    asm volatile("mma.sync.aligned.m16n8k16.row.col.f32.f16.f16.f32 "          \
        "{%0,%1,%2,%3},{%4,%5,%6,%7},{%8,%9},{%0,%1,%2,%3};"                   \
        : "+f"((d)[0]), "+f"((d)[1]), "+f"((d)[2]), "+f"((d)[3])               \
        : "r"(a0), "r"(a1), "r"(a2), "r"(a3), "r"(b0), "r"(b1))

__device__ __forceinline__ uint32_t fkey(float f) {
    uint32_t u = __float_as_uint(f);
    return u ^ ((u & 0x80000000u) ? 0xFFFFFFFFu : 0x80000000u);
}
__device__ __forceinline__ float unfkey(uint32_t k) {
    uint32_t u = (k & 0x80000000u) ? (k ^ 0x80000000u) : ~k;
    return __uint_as_float(u);
}

// ---------------------------------------------------------------------------
__global__ void convert_kernel(const float* __restrict__ src,
                               __half* __restrict__ d0, int n) {
    int i = blockIdx.x * blockDim.x + threadIdx.x;
    if (i == 0) g_cnt = 0;
    if (i < n) d0[i] = __float2half_rn(src[i]);
}

__global__ void rownorm_kernel(const float* __restrict__ src,
                               float* __restrict__ dst, int rows) {
    int w = (blockIdx.x * blockDim.x + threadIdx.x) >> 5;
    int lane = threadIdx.x & 31;
    if (w >= rows) return;
    const float4* p = (const float4*)(src + (size_t)w * CDIM);
    float s = 0.f;
    #pragma unroll
    for (int i = lane; i < CDIM / 4; i += 32) {
        float4 v = p[i];
        s += v.x * v.x + v.y * v.y + v.z * v.z + v.w * v.w;
    }
    #pragma unroll
    for (int o = 16; o; o >>= 1) s += __shfl_xor_sync(0xffffffffu, s, o);
    if (lane == 0) dst[w] = s;
}

// ---------------------------------------------------------------------------
// Phase 1: approx GEMM ((h0+h1)*c0 exact x.c0, fp32 acc) + top-2 + margin.
// 256 threads = 8 warps as 2(m) x 4(n), warp tile 64x64. B frags shared
// between the h0 and h1 passes (c0 only ever loaded).
// ---------------------------------------------------------------------------
__global__ void __launch_bounds__(THREADS, 1)
mma_argmin_kernel(const float* __restrict__ x, int kcb) {
    extern __shared__ char smem[];
    const uint32_t sb = smem_u32(smem);
    const int tid = threadIdx.x;
    const int wid = tid >> 5, lane = tid & 31;
    const int warp_m = wid & 1, warp_n = wid >> 1;     // 2 x 4
    const int rowBase = blockIdx.x * M_TILE;
    const int nChunks = kcb / N_CHUNK;            // 4
    const int S = nChunks * 4;                    // 16 B-stages

    // ---- B stage loader (c0 only) ----
    auto load_B = [&](int s) {
        const int c = s >> 2, kc = s & 3;
        const char* bsrc = (const char*)(g_c0 + (size_t)(c * N_CHUNK) * CDIM + kc * KT);
        const uint32_t bb = sb + SM_B + (s % NBUF) * BSTG;
        #pragma unroll
        for (int i = 0; i < 8; i++) {
            int u = tid + THREADS * i;
            int r = u >> 3, q = u & 7;
            CP_ASYNC16(bb + r * ROWB + ((q ^ (r & 7)) * 16),
                       bsrc + (size_t)r * (CDIM * 2) + q * 16);
        }
        CP_COMMIT();
    };

    load_B(0);
    load_B(1);

    // ---- on-the-fly A split: h0 -> subtiles 0..3, h1 -> subtiles 4..7 ----
    {
        const float* xsrc = x + (size_t)rowBase * CDIM;
        #pragma unroll 4
        for (int i = 0; i < 32; i++) {
            int u = tid + THREADS * i;          // float4 index
            int row = u >> 6;
            int coloff = (u & 63) * 4;
            float4 v = *(const float4*)(xsrc + (size_t)row * CDIM + coloff);
            __half a0 = __float2half_rn(v.x), a1 = __float2half_rn(v.y);
            __half a2 = __float2half_rn(v.z), a3 = __float2half_rn(v.w);
            __half b0 = __float2half_rn(v.x - __half2float(a0));
            __half b1 = __float2half_rn(v.y - __half2float(a1));
            __half b2 = __float2half_rn(v.z - __half2float(a2));
            __half b3 = __float2half_rn(v.w - __half2float(a3));
            int kc = coloff >> 6;
            int c  = coloff & 63;
            uint32_t off = (uint32_t)row * ROWB +
                           ((uint32_t)(((c >> 3) ^ (row & 7))) * 16) + ((c & 7) * 2);
            __half2 h0lo = __halves2half2(a0, a1), h0hi = __halves2half2(a2, a3);
            __half2 h1lo = __halves2half2(b0, b1), h1hi = __halves2half2(b2, b3);
            uint32_t d0 = sb + SM_A + kc * ASUB + off;
            uint32_t d1 = sb + SM_A + (4 + kc) * ASUB + off;
            asm volatile("st.shared.v2.b32 [%0], {%1,%2};" ::
                "r"(d0), "r"(*(uint32_t*)&h0lo), "r"(*(uint32_t*)&h0hi));
            asm volatile("st.shared.v2.b32 [%0], {%1,%2};" ::
                "r"(d1), "r"(*(uint32_t*)&h1lo), "r"(*(uint32_t*)&h1hi));
        }
    }

    // red arrays
    unsigned long long* red1 = (unsigned long long*)(smem + SM_RED);
    unsigned int* red2 = (unsigned int*)(smem + SM_RED + 128 * 8);
    for (int i = tid; i < M_TILE; i += THREADS) {
        red1[i] = 0xFFFFFFFFFFFFFFFFull;
        red2[i] = 0xFFFFFFFFu;
    }

    // ldmatrix address components
    const int lrow = lane & 15;
    const int hi   = lane >> 4;
    const int xorl = lrow & 7;
    uint32_t arow[4], brow[4];
    #pragma unroll
    for (int mt = 0; mt < 4; mt++)
        arow[mt] = (warp_m * 64 + mt * 16 + lrow) * ROWB;
    #pragma unroll
    for (int p = 0; p < 4; p++)
        brow[p] = (warp_n * 64 + p * 16 + lrow) * ROWB;

    float acc[4][8][4];
    #pragma unroll
    for (int mt = 0; mt < 4; mt++)
        #pragma unroll
        for (int nt = 0; nt < 8; nt++)
            #pragma unroll
            for (int e = 0; e < 4; e++) acc[mt][nt][e] = 0.f;

    float best[8], best2[8];
    int   bidx[8];
    #pragma unroll
    for (int i = 0; i < 8; i++) { best[i] = 3.4e38f; best2[i] = 3.4e38f; bidx[i] = 0; }

    for (int s = 0; s < S; s++) {
        if (s == S - 1) CP_WAIT0(); else CP_WAIT1();
        __syncthreads();
        if (s + 2 < S) load_B(s + 2);

        const int kc = s & 3;
        const uint32_t ab0 = sb + SM_A + kc * ASUB;
        const uint32_t ab1 = sb + SM_A + (4 + kc) * ASUB;
        const uint32_t bb = sb + SM_B + (s % NBUF) * BSTG;

        #pragma unroll
        for (int ks = 0; ks < 4; ks++) {
            const uint32_t koff = ((uint32_t)((ks * 2 + hi) ^ xorl)) * 16;
            uint32_t br[8][2];
            #pragma unroll
            for (int p = 0; p < 4; p++) {
                uint32_t r0, r1, r2, r3;
                LDSM_X4(r0, r1, r2, r3, bb + brow[p] + koff);
                br[2 * p][0] = r0; br[2 * p][1] = r2;
                br[2 * p + 1][0] = r1; br[2 * p + 1][1] = r3;
            }
            uint32_t ar0[4][4];
            #pragma unroll
            for (int mt = 0; mt < 4; mt++)
                LDSM_X4(ar0[mt][0], ar0[mt][1], ar0[mt][2], ar0[mt][3],
                        ab0 + arow[mt] + koff);
            #pragma unroll
            for (int mt = 0; mt < 4; mt++)
                #pragma unroll
                for (int nt = 0; nt < 8; nt++)
                    MMA16816(acc[mt][nt],
                             ar0[mt][0], ar0[mt][1], ar0[mt][2], ar0[mt][3],
                             br[nt][0], br[nt][1]);
            uint32_t ar1[4][4];
            #pragma unroll
            for (int mt = 0; mt < 4; mt++)
                LDSM_X4(ar1[mt][0], ar1[mt][1], ar1[mt][2], ar1[mt][3],
                        ab1 + arow[mt] + koff);
            #pragma unroll
            for (int mt = 0; mt < 4; mt++)
                #pragma unroll
                for (int nt = 0; nt < 8; nt++)
                    MMA16816(acc[mt][nt],
                             ar1[mt][0], ar1[mt][1], ar1[mt][2], ar1[mt][3],
                             br[nt][0], br[nt][1]);
        }

        // ---- chunk epilogue: score + top-2 update ----
        if (kc == 3) {
            const int c = s >> 2;
            const int colBase = c * N_CHUNK + warp_n * 64 + (lane & 3) * 2;
            #pragma unroll
            for (int nt = 0; nt < 8; nt++) {
                const int n0 = colBase + nt * 8;
                float2 e2v = *(const float2*)&g_e2[n0];
                #pragma unroll
                for (int mt = 0; mt < 4; mt++) {
                    float sc[4];
                    sc[0] = e2v.x - 2.f * acc[mt][nt][0];
                    sc[1] = e2v.y - 2.f * acc[mt][nt][1];
                    sc[2] = e2v.x - 2.f * acc[mt][nt][2];
                    sc[3] = e2v.y - 2.f * acc[mt][nt][3];
                    #pragma unroll
                    for (int e = 0; e < 4; e++) {
                        int slot = mt * 2 + (e >> 1);
                        int col  = n0 + (e & 1);
                        if (sc[e] < best[slot]) {
                            best2[slot] = best[slot];
                            best[slot] = sc[e];
                            bidx[slot] = col;
                        } else if (sc[e] < best2[slot]) {
                            best2[slot] = sc[e];
                        }
                        acc[mt][nt][e] = 0.f;
                    }
                }
            }
        }
    }

    // ---- cross-thread top-2 merge ----
    __syncthreads();
    #pragma unroll
    for (int slot = 0; slot < 8; slot++) {
        int mt = slot >> 1, h = slot & 1;
        int rl = warp_m * 64 + mt * 16 + (lane >> 2) + h * 8;
        unsigned long long pk =
            ((unsigned long long)fkey(best[slot]) << 32) |
            (unsigned long long)(uint32_t)bidx[slot];
        atomicMin(&red1[rl], pk);
    }
    __syncthreads();
    #pragma unroll
    for (int slot = 0; slot < 8; slot++) {
        int mt = slot >> 1, h = slot & 1;
        int rl = warp_m * 64 + mt * 16 + (lane >> 2) + h * 8;
        int widx = (int)(red1[rl] & 0xFFFFFFFFu);
        float cand = (bidx[slot] == widx) ? best2[slot] : best[slot];
        atomicMin(&red2[rl], fkey(cand));
    }
    __syncthreads();
    if (tid < M_TILE) {
        unsigned long long pk = red1[tid];
        float b1 = unfkey((uint32_t)(pk >> 32));
        float b2 = unfkey(red2[tid]);
        int row = rowBase + tid;
        g_idx[row] = (int)(pk & 0xFFFFFFFFu);
        g_partial[row] = g_x2s[row] + b1;
        if (b2 - b1 < MARGIN) {
            int p = atomicAdd(&g_cnt, 1);
            g_list[p] = row;
        }
    }
}

// ---------------------------------------------------------------------------
// Phase 2: exact fp32 re-scoring, FB_R flagged rows per block (compacted).
// ---------------------------------------------------------------------------
__global__ void __launch_bounds__(256, 4)
exact_fallback_kernel(const float* __restrict__ x,
                      const float* __restrict__ cb, int kcb) {
    int base = blockIdx.x * FB_R;
    int cnt = g_cnt;
    if (base >= cnt) return;
    int nr = min(FB_R, cnt - base);

    __shared__ float xs[FB_R][CDIM];
    __shared__ int rowids[FB_R];
    __shared__ unsigned long long red[FB_R];
    int t = threadIdx.x;   // 256
    if (t < FB_R) {
        red[t] = 0xFFFFFFFFFFFFFFFFull;
        rowids[t] = (t < nr) ? g_list[base + t] : -1;
    }
    __syncthreads();
    for (int i = t; i < nr * (CDIM / 4); i += 256) {
        int r = i >> 6, c4 = i & 63;
        ((float4*)xs[r])[c4] =
            ((const float4*)(x + (size_t)rowids[r] * CDIM))[c4];
    }
    __syncthreads();

    float bestv[FB_R];
    int   bestk[FB_R];
    #pragma unroll
    for (int r = 0; r < FB_R; r++) { bestv[r] = 3.4e38f; bestk[r] = 0; }

    for (int j = 0; j < kcb; j += 256) {
        int k = t + j;
        const float4* c4p = (const float4*)(cb + (size_t)k * CDIM);
        float acc[FB_R];
        #pragma unroll
        for (int r = 0; r < FB_R; r++) acc[r] = 0.f;
        #pragma unroll 4
        for (int d = 0; d < CDIM / 4; d++) {
            float4 c = c4p[d];
            #pragma unroll
            for (int r = 0; r < FB_R; r++) {
                float4 xv = ((const float4*)xs[r])[d];
                acc[r] += c.x * xv.x + c.y * xv.y + c.z * xv.z + c.w * xv.w;
            }
        }
        float e2k = g_e2[k];
        #pragma unroll
        for (int r = 0; r < FB_R; r++) {
            float sc = e2k - 2.f * acc[r];
            if (sc < bestv[r]) { bestv[r] = sc; bestk[r] = k; }
        }
    }
    #pragma unroll
    for (int r = 0; r < FB_R; r++) {
        if (r < nr) {
            unsigned long long pk =
                ((unsigned long long)fkey(bestv[r]) << 32) |
                (unsigned long long)(uint32_t)bestk[r];
            atomicMin(&red[r], pk);
        }
    }
    __syncthreads();
    if (t < nr) {
        unsigned long long pk = red[t];
        int row = rowids[t];
        g_idx[row] = (int)(pk & 0xFFFFFFFFu);
        g_partial[row] = g_x2s[row] + unfkey((uint32_t)(pk >> 32));
    }
}

// ---------------------------------------------------------------------------
__global__ void gather_kernel(const float* __restrict__ cbk,
                              float* __restrict__ outq,
                              float* __restrict__ outidx) {
    int row = blockIdx.x;
    int t = threadIdx.x;   // 64
    int idx = g_idx[row];
    float4 q = *(const float4*)(cbk + (size_t)idx * CDIM + t * 4);
    *(float4*)(outq + (size_t)row * CDIM + t * 4) = q;
    if (t == 0 && outidx) outidx[row] = (float)idx;
}

__global__ void finalize_kernel(float* __restrict__ outloss, int rows, int qn) {
    __shared__ double sh[1024];
    const float4* p4 = (const float4*)g_partial;
    double s = 0.0;
    for (int i = threadIdx.x; i < rows / 4; i += 1024) {
        float4 v = p4[i];
        s += (double)v.x + (double)v.y + (double)v.z + (double)v.w;
    }
    sh[threadIdx.x] = s;
    __syncthreads();
    for (int st = 512; st; st >>= 1) {
        if (threadIdx.x < st) sh[threadIdx.x] += sh[threadIdx.x + st];
        __syncthreads();
    }
    if (threadIdx.x == 0)
        *outloss = (float)(1.25 * sh[0] / (double)qn);
}

// ---------------------------------------------------------------------------
extern "C" void kernel_launch(void* const* d_in, const int* in_sizes, int n_in,
                              void* d_out, int out_size) {
    const float* x  = (const float*)d_in[0];
    const float* cb = (const float*)d_in[1];
    float* out = (float*)d_out;

    const int qn   = in_sizes[0];          // 8*4096*256
    const int kcb  = in_sizes[1] / CDIM;   // 1024
    const int rows = qn / CDIM;            // 32768

    __half *pc0;
    float *pe2, *px2;
    cudaGetSymbolAddress((void**)&pc0, g_c0);
    cudaGetSymbolAddress((void**)&pe2, g_e2);
    cudaGetSymbolAddress((void**)&px2, g_x2s);

    convert_kernel<<<(kcb * CDIM + 255) / 256, 256>>>(cb, pc0, kcb * CDIM);
    rownorm_kernel<<<(kcb * 32 + 255) / 256, 256>>>(cb, pe2, kcb);
    rownorm_kernel<<<(rows * 32 + 255) / 256, 256>>>(x, px2, rows);

    cudaFuncSetAttribute(mma_argmin_kernel,
                         cudaFuncAttributeMaxDynamicSharedMemorySize, SMEM_TOTAL);
    mma_argmin_kernel<<<rows / M_TILE, THREADS, SMEM_TOTAL>>>(x, kcb);

    exact_fallback_kernel<<<rows / FB_R, 256>>>(x, cb, kcb);

    bool has_loss = out_size >= qn + 1;
    bool has_idx  = out_size >= qn + 1 + rows;
    float* outidx = has_idx ? (out + qn + 1) : nullptr;

    gather_kernel<<<rows, 64>>>(cb, out, outidx);
    if (has_loss)
        finalize_kernel<<<1, 1024>>>(out + qn, rows, qn);
}

// round 14
// speedup vs baseline: 1.9257x; 1.0490x over previous
#include <cuda_runtime.h>
#include <cuda_fp16.h>
#include <cstdint>

#define CDIM 256
#define MAX_ROWS 32768
#define MAX_KCB  4096

#define M_TILE 128
#define N_CHUNK 128
#define KT 64                 // halfs per k-window (= 128 B per row)
#define ROWB 128
#define THREADS 256
#define MARGIN 0.15f
#define FB_R 16

// smem (occ 2): 3 stages of (A 16KB + B 16KB), then reduction arrays
#define ASTG    (M_TILE * ROWB)             // 16384
#define STG     (2 * ASTG)                  // 32768
#define NBUF    3
#define SM_RED  (NBUF * STG)                // 98304
#define SMEM_TOTAL (SM_RED + 128 * 8 + 128 * 4)   // 99840 (x2 CTA <= 227KB)

// ---------------- device globals ----------------
__device__ int    g_idx[MAX_ROWS];
__device__ int    g_list[MAX_ROWS];
__device__ int    g_cnt;
__device__ float  g_e2[MAX_KCB];
__device__ float  g_partial[MAX_ROWS];
__device__ float  g_x2s[MAX_ROWS];
__device__ __half g_x0[MAX_ROWS * CDIM];
__device__ __half g_c0[MAX_KCB * CDIM];

// ---------------- PTX helpers ----------------
__device__ __forceinline__ uint32_t smem_u32(const void* p) {
    uint32_t a;
    asm("{ .reg .u64 t; cvta.to.shared.u64 t, %1; cvt.u32.u64 %0, t; }"
        : "=r"(a) : "l"(p));
    return a;
}

#define CP_ASYNC16(dst, src) \
    asm volatile("cp.async.cg.shared.global [%0], [%1], 16;" :: "r"(dst), "l"(src))
#define CP_COMMIT()  asm volatile("cp.async.commit_group;")
#define CP_WAIT1()   asm volatile("cp.async.wait_group 1;")
#define CP_WAIT0()   asm volatile("cp.async.wait_group 0;")

#define LDSM_X4(r0, r1, r2, r3, addr)                                          \
    asm volatile("ldmatrix.sync.aligned.m8n8.x4.shared.b16 {%0,%1,%2,%3}, [%4];" \
        : "=r"(r0), "=r"(r1), "=r"(r2), "=r"(r3) : "r"(addr))

#define MMA16816(d, a0, a1, a2, a3, b0, b1)                                    \
    asm volatile("mma.sync.aligned.m16n8k16.row.col.f32.f16.f16.f32 "          \
        "{%0,%1,%2,%3},{%4,%5,%6,%7},{%8,%9},{%0,%1,%2,%3};"                   \
        : "+f"((d)[0]), "+f"((d)[1]), "+f"((d)[2]), "+f"((d)[3])               \
        : "r"(a0), "r"(a1), "r"(a2), "r"(a3), "r"(b0), "r"(b1))

__device__ __forceinline__ uint32_t fkey(float f) {
    uint32_t u = __float_as_uint(f);
    return u ^ ((u & 0x80000000u) ? 0xFFFFFFFFu : 0x80000000u);
}
__device__ __forceinline__ float unfkey(uint32_t k) {
    uint32_t u = (k & 0x80000000u) ? (k ^ 0x80000000u) : ~k;
    return __uint_as_float(u);
}

// ---------------------------------------------------------------------------
// fused convert: fp32 -> fp16 row + ||row||^2. One warp per row.
// ---------------------------------------------------------------------------
__global__ void convert_kernel(const float* __restrict__ src,
                               __half* __restrict__ dsth,
                               float* __restrict__ dstn, int rows) {
    int row = blockIdx.x * 8 + (threadIdx.x >> 5);
    int lane = threadIdx.x & 31;
    if (blockIdx.x == 0 && threadIdx.x == 0) g_cnt = 0;
    if (row >= rows) return;
    const float4* p = (const float4*)(src + (size_t)row * CDIM);
    float s = 0.f;
    #pragma unroll
    for (int i = 0; i < 2; i++) {
        int c4 = lane + 32 * i;
        float4 v = p[c4];
        s += v.x * v.x + v.y * v.y + v.z * v.z + v.w * v.w;
        __half2 lo = __halves2half2(__float2half_rn(v.x), __float2half_rn(v.y));
        __half2 hi = __halves2half2(__float2half_rn(v.z), __float2half_rn(v.w));
        uint2 pk = make_uint2(*(uint32_t*)&lo, *(uint32_t*)&hi);
        *(uint2*)(dsth + (size_t)row * CDIM + c4 * 4) = pk;
    }
    #pragma unroll
    for (int o = 16; o; o >>= 1) s += __shfl_xor_sync(0xffffffffu, s, o);
    if (lane == 0) dstn[row] = s;
}

// ---------------------------------------------------------------------------
// Phase 1: approx GEMM (h0*c0, fp32 acc) + top-2 argmin + margin flag.
// 256 threads = 8 warps as 2(m) x 4(n), warp tile 64x32, N_CHUNK=128.
// Streaming A+B stages, NBUF=3, occ 2, one wave (grid 256 <= 296 slots).
// ---------------------------------------------------------------------------
__global__ void __launch_bounds__(THREADS, 2)
mma_argmin_kernel(int kcb) {
    extern __shared__ char smem[];
    const uint32_t sb = smem_u32(smem);
    const int tid = threadIdx.x;
    const int wid = tid >> 5, lane = tid & 31;
    const int warp_m = wid & 1, warp_n = wid >> 1;     // 2 x 4
    const int rowBase = blockIdx.x * M_TILE;
    const int nChunks = kcb / N_CHUNK;            // 8
    const int S = nChunks * 4;                    // 32 stages

    // ---- stage loader: A(rowBase, kc) + B(chunk c, kc) ----
    auto load_stage = [&](int s) {
        const int c = s >> 2, kc = s & 3;
        const char* asrc = (const char*)(g_x0 + (size_t)rowBase * CDIM + kc * KT);
        const char* bsrc = (const char*)(g_c0 + (size_t)(c * N_CHUNK) * CDIM + kc * KT);
        const uint32_t ab = sb + (s % NBUF) * STG;
        const uint32_t bb = ab + ASTG;
        #pragma unroll
        for (int i = 0; i < 4; i++) {              // 1024 units each
            int u = tid + THREADS * i;
            int r = u >> 3, q = u & 7;
            uint32_t so = r * ROWB + ((q ^ (r & 7)) * 16);
            CP_ASYNC16(ab + so, asrc + (size_t)r * (CDIM * 2) + q * 16);
            CP_ASYNC16(bb + so, bsrc + (size_t)r * (CDIM * 2) + q * 16);
        }
        CP_COMMIT();
    };

    load_stage(0);
    load_stage(1);

    // red arrays
    unsigned long long* red1 = (unsigned long long*)(smem + SM_RED);
    unsigned int* red2 = (unsigned int*)(smem + SM_RED + 128 * 8);
    for (int i = tid; i < M_TILE; i += THREADS) {
        red1[i] = 0xFFFFFFFFFFFFFFFFull;
        red2[i] = 0xFFFFFFFFu;
    }

    // ldmatrix address components
    const int lrow = lane & 15;
    const int hi   = lane >> 4;
    const int xorl = lrow & 7;
    uint32_t arow[4], brow[2];
    #pragma unroll
    for (int mt = 0; mt < 4; mt++)
        arow[mt] = (warp_m * 64 + mt * 16 + lrow) * ROWB;
    #pragma unroll
    for (int p = 0; p < 2; p++)
        brow[p] = (warp_n * 32 + p * 16 + lrow) * ROWB;

    float acc[4][4][4];
    #pragma unroll
    for (int mt = 0; mt < 4; mt++)
        #pragma unroll
        for (int nt = 0; nt < 4; nt++)
            #pragma unroll
            for (int e = 0; e < 4; e++) acc[mt][nt][e] = 0.f;

    float best[8], best2[8];
    int   bidx[8];
    #pragma unroll
    for (int i = 0; i < 8; i++) { best[i] = 3.4e38f; best2[i] = 3.4e38f; bidx[i] = 0; }

    for (int s = 0; s < S; s++) {
        if (s == S - 1) CP_WAIT0(); else CP_WAIT1();
        __syncthreads();
        if (s + 2 < S) load_stage(s + 2);

        const uint32_t ab = sb + (s % NBUF) * STG;
        const uint32_t bb = ab + ASTG;

        #pragma unroll
        for (int ks = 0; ks < 4; ks++) {
            const uint32_t koff = ((uint32_t)((ks * 2 + hi) ^ xorl)) * 16;
            uint32_t ar[4][4];
            uint32_t br[4][2];
            #pragma unroll
            for (int p = 0; p < 2; p++) {
                uint32_t r0, r1, r2, r3;
                LDSM_X4(r0, r1, r2, r3, bb + brow[p] + koff);
                br[2 * p][0] = r0; br[2 * p][1] = r2;
                br[2 * p + 1][0] = r1; br[2 * p + 1][1] = r3;
            }
            #pragma unroll
            for (int mt = 0; mt < 4; mt++)
                LDSM_X4(ar[mt][0], ar[mt][1], ar[mt][2], ar[mt][3],
                        ab + arow[mt] + koff);
            #pragma unroll
            for (int mt = 0; mt < 4; mt++)
                #pragma unroll
                for (int nt = 0; nt < 4; nt++)
                    MMA16816(acc[mt][nt],
                             ar[mt][0], ar[mt][1], ar[mt][2], ar[mt][3],
                             br[nt][0], br[nt][1]);
        }

        // ---- chunk epilogue: score + top-2 update ----
        if ((s & 3) == 3) {
            const int c = s >> 2;
            const int colBase = c * N_CHUNK + warp_n * 32 + (lane & 3) * 2;
            #pragma unroll
            for (int nt = 0; nt < 4; nt++) {
                const int n0 = colBase + nt * 8;
                float2 e2v = *(const float2*)&g_e2[n0];
                #pragma unroll
                for (int mt = 0; mt < 4; mt++) {
                    float sc[4];
                    sc[0] = e2v.x - 2.f * acc[mt][nt][0];
                    sc[1] = e2v.y - 2.f * acc[mt][nt][1];
                    sc[2] = e2v.x - 2.f * acc[mt][nt][2];
                    sc[3] = e2v.y - 2.f * acc[mt][nt][3];
                    #pragma unroll
                    for (int e = 0; e < 4; e++) {
                        int slot = mt * 2 + (e >> 1);
                        int col  = n0 + (e & 1);
                        if (sc[e] < best[slot]) {
                            best2[slot] = best[slot];
                            best[slot] = sc[e];
                            bidx[slot] = col;
                        } else if (sc[e] < best2[slot]) {
                            best2[slot] = sc[e];
                        }
                        acc[mt][nt][e] = 0.f;
                    }
                }
            }
        }
    }

    // ---- cross-thread top-2 merge ----
    __syncthreads();
    #pragma unroll
    for (int slot = 0; slot < 8; slot++) {
        int mt = slot >> 1, h = slot & 1;
        int rl = warp_m * 64 + mt * 16 + (lane >> 2) + h * 8;
        unsigned long long pk =
            ((unsigned long long)fkey(best[slot]) << 32) |
            (unsigned long long)(uint32_t)bidx[slot];
        atomicMin(&red1[rl], pk);
    }
    __syncthreads();
    #pragma unroll
    for (int slot = 0; slot < 8; slot++) {
        int mt = slot >> 1, h = slot & 1;
        int rl = warp_m * 64 + mt * 16 + (lane >> 2) + h * 8;
        int widx = (int)(red1[rl] & 0xFFFFFFFFu);
        float cand = (bidx[slot] == widx) ? best2[slot] : best[slot];
        atomicMin(&red2[rl], fkey(cand));
    }
    __syncthreads();
    if (tid < M_TILE) {
        unsigned long long pk = red1[tid];
        float b1 = unfkey((uint32_t)(pk >> 32));
        float b2 = unfkey(red2[tid]);
        int row = rowBase + tid;
        g_idx[row] = (int)(pk & 0xFFFFFFFFu);
        g_partial[row] = g_x2s[row] + b1;
        if (b2 - b1 < MARGIN) {
            int p = atomicAdd(&g_cnt, 1);
            g_list[p] = row;
        }
    }
}

// ---------------------------------------------------------------------------
// Phase 2: exact fp32 re-scoring, FB_R flagged rows per block (compacted).
// ---------------------------------------------------------------------------
__global__ void __launch_bounds__(256, 4)
exact_fallback_kernel(const float* __restrict__ x,
                      const float* __restrict__ cb, int kcb) {
    int base = blockIdx.x * FB_R;
    int cnt = g_cnt;
    if (base >= cnt) return;
    int nr = min(FB_R, cnt - base);

    __shared__ float xs[FB_R][CDIM];
    __shared__ int rowids[FB_R];
    __shared__ unsigned long long red[FB_R];
    int t = threadIdx.x;   // 256
    if (t < FB_R) {
        red[t] = 0xFFFFFFFFFFFFFFFFull;
        rowids[t] = (t < nr) ? g_list[base + t] : -1;
    }
    __syncthreads();
    for (int i = t; i < nr * (CDIM / 4); i += 256) {
        int r = i >> 6, c4 = i & 63;
        ((float4*)xs[r])[c4] =
            ((const float4*)(x + (size_t)rowids[r] * CDIM))[c4];
    }
    __syncthreads();

    float bestv[FB_R];
    int   bestk[FB_R];
    #pragma unroll
    for (int r = 0; r < FB_R; r++) { bestv[r] = 3.4e38f; bestk[r] = 0; }

    for (int j = 0; j < kcb; j += 256) {
        int k = t + j;
        const float4* c4p = (const float4*)(cb + (size_t)k * CDIM);
        float acc[FB_R];
        #pragma unroll
        for (int r = 0; r < FB_R; r++) acc[r] = 0.f;
        #pragma unroll 2
        for (int d = 0; d < CDIM / 4; d++) {
            float4 c = c4p[d];
            #pragma unroll
            for (int r = 0; r < FB_R; r++) {
                float4 xv = ((const float4*)xs[r])[d];
                acc[r] += c.x * xv.x + c.y * xv.y + c.z * xv.z + c.w * xv.w;
            }
        }
        float e2k = g_e2[k];
        #pragma unroll
        for (int r = 0; r < FB_R; r++) {
            float sc = e2k - 2.f * acc[r];
            if (sc < bestv[r]) { bestv[r] = sc; bestk[r] = k; }
        }
    }
    #pragma unroll
    for (int r = 0; r < FB_R; r++) {
        if (r < nr) {
            unsigned long long pk =
                ((unsigned long long)fkey(bestv[r]) << 32) |
                (unsigned long long)(uint32_t)bestk[r];
            atomicMin(&red[r], pk);
        }
    }
    __syncthreads();
    if (t < nr) {
        unsigned long long pk = red[t];
        int row = rowids[t];
        g_idx[row] = (int)(pk & 0xFFFFFFFFu);
        g_partial[row] = g_x2s[row] + unfkey((uint32_t)(pk >> 32));
    }
}

// ---------------------------------------------------------------------------
__global__ void gather_kernel(const float* __restrict__ cbk,
                              float* __restrict__ outq,
                              float* __restrict__ outidx) {
    int row = blockIdx.x;
    int t = threadIdx.x;   // 64
    int idx = g_idx[row];
    float4 q = *(const float4*)(cbk + (size_t)idx * CDIM + t * 4);
    *(float4*)(outq + (size_t)row * CDIM + t * 4) = q;
    if (t == 0 && outidx) outidx[row] = (float)idx;
}

__global__ void finalize_kernel(float* __restrict__ outloss, int rows, int qn) {
    __shared__ double sh[1024];
    const float4* p4 = (const float4*)g_partial;
    double s = 0.0;
    for (int i = threadIdx.x; i < rows / 4; i += 1024) {
        float4 v = p4[i];
        s += (double)v.x + (double)v.y + (double)v.z + (double)v.w;
    }
    sh[threadIdx.x] = s;
    __syncthreads();
    for (int st = 512; st; st >>= 1) {
        if (threadIdx.x < st) sh[threadIdx.x] += sh[threadIdx.x + st];
        __syncthreads();
    }
    if (threadIdx.x == 0)
        *outloss = (float)(1.25 * sh[0] / (double)qn);
}

// ---------------------------------------------------------------------------
extern "C" void kernel_launch(void* const* d_in, const int* in_sizes, int n_in,
                              void* d_out, int out_size) {
    const float* x  = (const float*)d_in[0];
    const float* cb = (const float*)d_in[1];
    float* out = (float*)d_out;

    const int qn   = in_sizes[0];          // 8*4096*256
    const int kcb  = in_sizes[1] / CDIM;   // 1024
    const int rows = qn / CDIM;            // 32768

    __half *px0, *pc0;
    float *pe2, *px2;
    cudaGetSymbolAddress((void**)&px0, g_x0);
    cudaGetSymbolAddress((void**)&pc0, g_c0);
    cudaGetSymbolAddress((void**)&pe2, g_e2);
    cudaGetSymbolAddress((void**)&px2, g_x2s);

    convert_kernel<<<(rows + 7) / 8, 256>>>(x, px0, px2, rows);
    convert_kernel<<<(kcb + 7) / 8, 256>>>(cb, pc0, pe2, kcb);

    cudaFuncSetAttribute(mma_argmin_kernel,
                         cudaFuncAttributeMaxDynamicSharedMemorySize, SMEM_TOTAL);
    mma_argmin_kernel<<<rows / M_TILE, THREADS, SMEM_TOTAL>>>(kcb);

    exact_fallback_kernel<<<rows / FB_R, 256>>>(x, cb, kcb);

    bool has_loss = out_size >= qn + 1;
    bool has_idx  = out_size >= qn + 1 + rows;
    float* outidx = has_idx ? (out + qn + 1) : nullptr;

    gather_kernel<<<rows, 64>>>(cb, out, outidx);
    if (has_loss)
        finalize_kernel<<<1, 1024>>>(out + qn, rows, qn);
}

// round 15
// speedup vs baseline: 2.4216x; 1.2575x over previous
#include <cuda_runtime.h>
#include <cuda_fp16.h>
#include <cstdint>

#define CDIM 256
#define MAX_ROWS 32768
#define MAX_KCB  4096

#define M_TILE 128
#define N_CHUNK 128
#define KT 64                 // halfs per k-window (= 128 B per row)
#define ROWB 128
#define THREADS 256
#define MARGIN 0.15f
#define FB_R 16

// smem (occ 2): 3 stages of (A 16KB + B 16KB), then reduction arrays
#define ASTG    (M_TILE * ROWB)             // 16384
#define STG     (2 * ASTG)                  // 32768
#define NBUF    3
#define SM_RED  (NBUF * STG)                // 98304
#define SMEM_TOTAL (SM_RED + 128 * 8 + 128 * 4)   // 99840 (x2 CTA <= 227KB)

// ---------------- device globals ----------------
__device__ int    g_idx[MAX_ROWS];
__device__ int    g_list[MAX_ROWS];
__device__ int    g_cnt;
__device__ float  g_e2[MAX_KCB];
__device__ float  g_partial[MAX_ROWS];
__device__ float  g_x2s[MAX_ROWS];
__device__ __half g_x0[MAX_ROWS * CDIM];
__device__ __half g_c0[MAX_KCB * CDIM];

// ---------------- PTX helpers ----------------
__device__ __forceinline__ uint32_t smem_u32(const void* p) {
    uint32_t a;
    asm("{ .reg .u64 t; cvta.to.shared.u64 t, %1; cvt.u32.u64 %0, t; }"
        : "=r"(a) : "l"(p));
    return a;
}

#define CP_ASYNC16(dst, src) \
    asm volatile("cp.async.cg.shared.global [%0], [%1], 16;" :: "r"(dst), "l"(src))
#define CP_COMMIT()  asm volatile("cp.async.commit_group;")
#define CP_WAIT1()   asm volatile("cp.async.wait_group 1;")
#define CP_WAIT0()   asm volatile("cp.async.wait_group 0;")

#define LDSM_X4(r0, r1, r2, r3, addr)                                          \
    asm volatile("ldmatrix.sync.aligned.m8n8.x4.shared.b16 {%0,%1,%2,%3}, [%4];" \
        : "=r"(r0), "=r"(r1), "=r"(r2), "=r"(r3) : "r"(addr))

#define MMA16816(d, a0, a1, a2, a3, b0, b1)                                    \
    asm volatile("mma.sync.aligned.m16n8k16.row.col.f32.f16.f16.f32 "          \
        "{%0,%1,%2,%3},{%4,%5,%6,%7},{%8,%9},{%0,%1,%2,%3};"                   \
        : "+f"((d)[0]), "+f"((d)[1]), "+f"((d)[2]), "+f"((d)[3])               \
        : "r"(a0), "r"(a1), "r"(a2), "r"(a3), "r"(b0), "r"(b1))

__device__ __forceinline__ uint32_t fkey(float f) {
    uint32_t u = __float_as_uint(f);
    return u ^ ((u & 0x80000000u) ? 0xFFFFFFFFu : 0x80000000u);
}
__device__ __forceinline__ float unfkey(uint32_t k) {
    uint32_t u = (k & 0x80000000u) ? (k ^ 0x80000000u) : ~k;
    return __uint_as_float(u);
}

// ---------------------------------------------------------------------------
// fused convert: fp32 -> fp16 row + ||row||^2. One warp per row.
// ---------------------------------------------------------------------------
__global__ void convert_kernel(const float* __restrict__ src,
                               __half* __restrict__ dsth,
                               float* __restrict__ dstn, int rows) {
    int row = blockIdx.x * 8 + (threadIdx.x >> 5);
    int lane = threadIdx.x & 31;
    if (blockIdx.x == 0 && threadIdx.x == 0) g_cnt = 0;
    if (row >= rows) return;
    const float4* p = (const float4*)(src + (size_t)row * CDIM);
    float s = 0.f;
    #pragma unroll
    for (int i = 0; i < 2; i++) {
        int c4 = lane + 32 * i;
        float4 v = p[c4];
        s += v.x * v.x + v.y * v.y + v.z * v.z + v.w * v.w;
        __half2 lo = __halves2half2(__float2half_rn(v.x), __float2half_rn(v.y));
        __half2 hi = __halves2half2(__float2half_rn(v.z), __float2half_rn(v.w));
        uint2 pk = make_uint2(*(uint32_t*)&lo, *(uint32_t*)&hi);
        *(uint2*)(dsth + (size_t)row * CDIM + c4 * 4) = pk;
    }
    #pragma unroll
    for (int o = 16; o; o >>= 1) s += __shfl_xor_sync(0xffffffffu, s, o);
    if (lane == 0) dstn[row] = s;
}

// ---------------------------------------------------------------------------
// Phase 1: approx GEMM (h0*c0, fp32 acc) + top-2 argmin + margin flag.
// 256 threads = 8 warps as 2(m) x 4(n), warp tile 64x32, N_CHUNK=128.
// Streaming A+B stages, NBUF=3, occ 2, one wave (grid 256 <= 296 slots).
// ---------------------------------------------------------------------------
__global__ void __launch_bounds__(THREADS, 2)
mma_argmin_kernel(int kcb) {
    extern __shared__ char smem[];
    const uint32_t sb = smem_u32(smem);
    const int tid = threadIdx.x;
    const int wid = tid >> 5, lane = tid & 31;
    const int warp_m = wid & 1, warp_n = wid >> 1;     // 2 x 4
    const int rowBase = blockIdx.x * M_TILE;
    const int nChunks = kcb / N_CHUNK;            // 8
    const int S = nChunks * 4;                    // 32 stages

    // ---- stage loader: A(rowBase, kc) + B(chunk c, kc) ----
    auto load_stage = [&](int s) {
        const int c = s >> 2, kc = s & 3;
        const char* asrc = (const char*)(g_x0 + (size_t)rowBase * CDIM + kc * KT);
        const char* bsrc = (const char*)(g_c0 + (size_t)(c * N_CHUNK) * CDIM + kc * KT);
        const uint32_t ab = sb + (s % NBUF) * STG;
        const uint32_t bb = ab + ASTG;
        #pragma unroll
        for (int i = 0; i < 4; i++) {              // 1024 units each
            int u = tid + THREADS * i;
            int r = u >> 3, q = u & 7;
            uint32_t so = r * ROWB + ((q ^ (r & 7)) * 16);
            CP_ASYNC16(ab + so, asrc + (size_t)r * (CDIM * 2) + q * 16);
            CP_ASYNC16(bb + so, bsrc + (size_t)r * (CDIM * 2) + q * 16);
        }
        CP_COMMIT();
    };

    load_stage(0);
    load_stage(1);

    // red arrays
    unsigned long long* red1 = (unsigned long long*)(smem + SM_RED);
    unsigned int* red2 = (unsigned int*)(smem + SM_RED + 128 * 8);
    for (int i = tid; i < M_TILE; i += THREADS) {
        red1[i] = 0xFFFFFFFFFFFFFFFFull;
        red2[i] = 0xFFFFFFFFu;
    }

    // ldmatrix address components
    const int lrow = lane & 15;
    const int hi   = lane >> 4;
    const int xorl = lrow & 7;
    uint32_t arow[4], brow[2];
    #pragma unroll
    for (int mt = 0; mt < 4; mt++)
        arow[mt] = (warp_m * 64 + mt * 16 + lrow) * ROWB;
    #pragma unroll
    for (int p = 0; p < 2; p++)
        brow[p] = (warp_n * 32 + p * 16 + lrow) * ROWB;

    float acc[4][4][4];
    #pragma unroll
    for (int mt = 0; mt < 4; mt++)
        #pragma unroll
        for (int nt = 0; nt < 4; nt++)
            #pragma unroll
            for (int e = 0; e < 4; e++) acc[mt][nt][e] = 0.f;

    float best[8], best2[8];
    int   bidx[8];
    #pragma unroll
    for (int i = 0; i < 8; i++) { best[i] = 3.4e38f; best2[i] = 3.4e38f; bidx[i] = 0; }

    for (int s = 0; s < S; s++) {
        if (s == S - 1) CP_WAIT0(); else CP_WAIT1();
        __syncthreads();
        if (s + 2 < S) load_stage(s + 2);

        const uint32_t ab = sb + (s % NBUF) * STG;
        const uint32_t bb = ab + ASTG;

        #pragma unroll
        for (int ks = 0; ks < 4; ks++) {
            const uint32_t koff = ((uint32_t)((ks * 2 + hi) ^ xorl)) * 16;
            uint32_t ar[4][4];
            uint32_t br[4][2];
            #pragma unroll
            for (int p = 0; p < 2; p++) {
                uint32_t r0, r1, r2, r3;
                LDSM_X4(r0, r1, r2, r3, bb + brow[p] + koff);
                br[2 * p][0] = r0; br[2 * p][1] = r2;
                br[2 * p + 1][0] = r1; br[2 * p + 1][1] = r3;
            }
            #pragma unroll
            for (int mt = 0; mt < 4; mt++)
                LDSM_X4(ar[mt][0], ar[mt][1], ar[mt][2], ar[mt][3],
                        ab + arow[mt] + koff);
            #pragma unroll
            for (int mt = 0; mt < 4; mt++)
                #pragma unroll
                for (int nt = 0; nt < 4; nt++)
                    MMA16816(acc[mt][nt],
                             ar[mt][0], ar[mt][1], ar[mt][2], ar[mt][3],
                             br[nt][0], br[nt][1]);
        }

        // ---- chunk epilogue: score + top-2 update ----
        if ((s & 3) == 3) {
            const int c = s >> 2;
            const int colBase = c * N_CHUNK + warp_n * 32 + (lane & 3) * 2;
            #pragma unroll
            for (int nt = 0; nt < 4; nt++) {
                const int n0 = colBase + nt * 8;
                float2 e2v = *(const float2*)&g_e2[n0];
                #pragma unroll
                for (int mt = 0; mt < 4; mt++) {
                    float sc[4];
                    sc[0] = e2v.x - 2.f * acc[mt][nt][0];
                    sc[1] = e2v.y - 2.f * acc[mt][nt][1];
                    sc[2] = e2v.x - 2.f * acc[mt][nt][2];
                    sc[3] = e2v.y - 2.f * acc[mt][nt][3];
                    #pragma unroll
                    for (int e = 0; e < 4; e++) {
                        int slot = mt * 2 + (e >> 1);
                        int col  = n0 + (e & 1);
                        if (sc[e] < best[slot]) {
                            best2[slot] = best[slot];
                            best[slot] = sc[e];
                            bidx[slot] = col;
                        } else if (sc[e] < best2[slot]) {
                            best2[slot] = sc[e];
                        }
                        acc[mt][nt][e] = 0.f;
                    }
                }
            }
        }
    }

    // ---- cross-thread top-2 merge ----
    __syncthreads();
    #pragma unroll
    for (int slot = 0; slot < 8; slot++) {
        int mt = slot >> 1, h = slot & 1;
        int rl = warp_m * 64 + mt * 16 + (lane >> 2) + h * 8;
        unsigned long long pk =
            ((unsigned long long)fkey(best[slot]) << 32) |
            (unsigned long long)(uint32_t)bidx[slot];
        atomicMin(&red1[rl], pk);
    }
    __syncthreads();
    #pragma unroll
    for (int slot = 0; slot < 8; slot++) {
        int mt = slot >> 1, h = slot & 1;
        int rl = warp_m * 64 + mt * 16 + (lane >> 2) + h * 8;
        int widx = (int)(red1[rl] & 0xFFFFFFFFu);
        float cand = (bidx[slot] == widx) ? best2[slot] : best[slot];
        atomicMin(&red2[rl], fkey(cand));
    }
    __syncthreads();
    if (tid < M_TILE) {
        unsigned long long pk = red1[tid];
        float b1 = unfkey((uint32_t)(pk >> 32));
        float b2 = unfkey(red2[tid]);
        int row = rowBase + tid;
        g_idx[row] = (int)(pk & 0xFFFFFFFFu);
        g_partial[row] = g_x2s[row] + b1;
        if (b2 - b1 < MARGIN) {
            int p = atomicAdd(&g_cnt, 1);
            g_list[p] = row;
        }
    }
}

// ---------------------------------------------------------------------------
// Phase 2: exact fp32 re-scoring, FB_R flagged rows per block (compacted).
// launch_bounds(256,2): 128-reg budget so acc[FB_R] stays in registers.
// ---------------------------------------------------------------------------
__global__ void __launch_bounds__(256, 2)
exact_fallback_kernel(const float* __restrict__ x,
                      const float* __restrict__ cb, int kcb) {
    int base = blockIdx.x * FB_R;
    int cnt = g_cnt;
    if (base >= cnt) return;
    int nr = min(FB_R, cnt - base);

    __shared__ float xs[FB_R][CDIM];
    __shared__ int rowids[FB_R];
    __shared__ unsigned long long red[FB_R];
    int t = threadIdx.x;   // 256
    if (t < FB_R) {
        red[t] = 0xFFFFFFFFFFFFFFFFull;
        rowids[t] = (t < nr) ? g_list[base + t] : -1;
    }
    __syncthreads();
    for (int i = t; i < nr * (CDIM / 4); i += 256) {
        int r = i >> 6, c4 = i & 63;
        ((float4*)xs[r])[c4] =
            ((const float4*)(x + (size_t)rowids[r] * CDIM))[c4];
    }
    __syncthreads();

    float bestv[FB_R];
    int   bestk[FB_R];
    #pragma unroll
    for (int r = 0; r < FB_R; r++) { bestv[r] = 3.4e38f; bestk[r] = 0; }

    for (int j = 0; j < kcb; j += 256) {
        int k = t + j;
        const float4* c4p = (const float4*)(cb + (size_t)k * CDIM);
        float acc[FB_R];
        #pragma unroll
        for (int r = 0; r < FB_R; r++) acc[r] = 0.f;
        #pragma unroll 2
        for (int d = 0; d < CDIM / 4; d++) {
            float4 c = c4p[d];
            #pragma unroll
            for (int r = 0; r < FB_R; r++) {
                float4 xv = ((const float4*)xs[r])[d];
                acc[r] += c.x * xv.x + c.y * xv.y + c.z * xv.z + c.w * xv.w;
            }
        }
        float e2k = g_e2[k];
        #pragma unroll
        for (int r = 0; r < FB_R; r++) {
            float sc = e2k - 2.f * acc[r];
            if (sc < bestv[r]) { bestv[r] = sc; bestk[r] = k; }
        }
    }
    #pragma unroll
    for (int r = 0; r < FB_R; r++) {
        if (r < nr) {
            unsigned long long pk =
                ((unsigned long long)fkey(bestv[r]) << 32) |
                (unsigned long long)(uint32_t)bestk[r];
            atomicMin(&red[r], pk);
        }
    }
    __syncthreads();
    if (t < nr) {
        unsigned long long pk = red[t];
        int row = rowids[t];
        g_idx[row] = (int)(pk & 0xFFFFFFFFu);
        g_partial[row] = g_x2s[row] + unfkey((uint32_t)(pk >> 32));
    }
}

// ---------------------------------------------------------------------------
__global__ void gather_kernel(const float* __restrict__ cbk,
                              float* __restrict__ outq,
                              float* __restrict__ outidx) {
    int row = blockIdx.x;
    int t = threadIdx.x;   // 64
    int idx = g_idx[row];
    float4 q = *(const float4*)(cbk + (size_t)idx * CDIM + t * 4);
    *(float4*)(outq + (size_t)row * CDIM + t * 4) = q;
    if (t == 0 && outidx) outidx[row] = (float)idx;
}

__global__ void finalize_kernel(float* __restrict__ outloss, int rows, int qn) {
    __shared__ double sh[1024];
    const float4* p4 = (const float4*)g_partial;
    double s = 0.0;
    for (int i = threadIdx.x; i < rows / 4; i += 1024) {
        float4 v = p4[i];
        s += (double)v.x + (double)v.y + (double)v.z + (double)v.w;
    }
    sh[threadIdx.x] = s;
    __syncthreads();
    for (int st = 512; st; st >>= 1) {
        if (threadIdx.x < st) sh[threadIdx.x] += sh[threadIdx.x + st];
        __syncthreads();
    }
    if (threadIdx.x == 0)
        *outloss = (float)(1.25 * sh[0] / (double)qn);
}

// ---------------------------------------------------------------------------
extern "C" void kernel_launch(void* const* d_in, const int* in_sizes, int n_in,
                              void* d_out, int out_size) {
    const float* x  = (const float*)d_in[0];
    const float* cb = (const float*)d_in[1];
    float* out = (float*)d_out;

    const int qn   = in_sizes[0];          // 8*4096*256
    const int kcb  = in_sizes[1] / CDIM;   // 1024
    const int rows = qn / CDIM;            // 32768

    __half *px0, *pc0;
    float *pe2, *px2;
    cudaGetSymbolAddress((void**)&px0, g_x0);
    cudaGetSymbolAddress((void**)&pc0, g_c0);
    cudaGetSymbolAddress((void**)&pe2, g_e2);
    cudaGetSymbolAddress((void**)&px2, g_x2s);

    convert_kernel<<<(rows + 7) / 8, 256>>>(x, px0, px2, rows);
    convert_kernel<<<(kcb + 7) / 8, 256>>>(cb, pc0, pe2, kcb);

    cudaFuncSetAttribute(mma_argmin_kernel,
                         cudaFuncAttributeMaxDynamicSharedMemorySize, SMEM_TOTAL);
    mma_argmin_kernel<<<rows / M_TILE, THREADS, SMEM_TOTAL>>>(kcb);

    exact_fallback_kernel<<<rows / FB_R, 256>>>(x, cb, kcb);

    bool has_loss = out_size >= qn + 1;
    bool has_idx  = out_size >= qn + 1 + rows;
    float* outidx = has_idx ? (out + qn + 1) : nullptr;

    gather_kernel<<<rows, 64>>>(cb, out, outidx);
    if (has_loss)
        finalize_kernel<<<1, 1024>>>(out + qn, rows, qn);
}